// round 14
// baseline (speedup 1.0000x reference)
#include <cuda_runtime.h>
#include <cuda_fp16.h>
#include <math.h>
#include <stdint.h>

#define Bq 16
#define NN 1024
#define DD 256
#define HH 128
#define LL 2

// ---------------- scratch (device globals; no allocation) ----------------
__device__ __align__(128) float  g_gate[Bq * NN];
__device__ __align__(128) __half g_Xt  [Bq * DD * NN];     // x^T [b,d,k] fp16
__device__ __align__(128) __half g_dep16[(size_t)Bq * NN * NN];
__device__ __align__(128) __half g_lat16[(size_t)Bq * NN * NN];
__device__ __align__(128) __half g_Yh[2][(size_t)Bq * NN * DD];  // Y hi plane per sel
__device__ __align__(128) __half g_Yl[2][(size_t)Bq * NN * DD];  // Y lo plane per sel
__device__ __align__(128) __half g_W16[2][HH * DD];
__device__ __align__(128) float  g_xmid[Bq * NN * DD];

// ---------------- helpers ----------------
__device__ __forceinline__ uint32_t smem_u32(const void* p) {
    uint32_t a;
    asm("{ .reg .u64 t; cvta.to.shared.u64 t, %1; cvt.u32.u64 %0, t; }" : "=r"(a) : "l"(p));
    return a;
}
__device__ __forceinline__ void cp16(uint32_t dst, const void* src) {
    asm volatile("cp.async.cg.shared.global [%0], [%1], 16;" :: "r"(dst), "l"(src) : "memory");
}
#define CP_COMMIT() asm volatile("cp.async.commit_group;" ::: "memory")
#define CP_WAIT0()  asm volatile("cp.async.wait_group 0;" ::: "memory")

#define MMAH(D, A, B) \
    asm volatile("mma.sync.aligned.m16n8k16.row.col.f32.f16.f16.f32 " \
        "{%0,%1,%2,%3}, {%4,%5,%6,%7}, {%8,%9}, {%0,%1,%2,%3};" \
        : "+f"((D)[0]), "+f"((D)[1]), "+f"((D)[2]), "+f"((D)[3]) \
        : "r"((A)[0]), "r"((A)[1]), "r"((A)[2]), "r"((A)[3]), \
          "r"((B)[0]), "r"((B)[1]))

// adjacency kernel smem geometry (halves)
#define BSTR 40
#define ASTR 40
#define MSTR 136                         // SEL1 k-major stride
#define B_TILE_H (256 * BSTR)            // 10240 halves
#define A_TILE_H (128 * ASTR)            // 5120 halves (>= 32*136)
#define ADJ_SMEM ((2 * B_TILE_H + 2 * A_TILE_H) * 2)   // 61440 bytes

// fc kernel smem
#define FC_AST 40
#define FCT (128 * FC_AST)               // 5120 halves per tile
#define FCS (6 * FCT)                    // 6 tiles per stage: Yhi0,Ylo0,Yhi1,Ylo1,W0,W1
#define FC_SMEM (128 * 260 * 4)          // 133120 bytes (hbuf phase dominates; 2*FCS*2=122880 fits)

extern __shared__ char smemc[];

// ---------------- K0: W -> fp16 (per layer) ----------------
__global__ void w16_kernel(const float* __restrict__ Wi, const float* __restrict__ Wo) {
    int i4 = (blockIdx.x * 256 + threadIdx.x) * 4;
    if (i4 >= HH * DD) return;
    float4 v = *(const float4*)(Wi + i4);
    __half2 h[2] = { __floats2half2_rn(v.x, v.y), __floats2half2_rn(v.z, v.w) };
    *(uint2*)(g_W16[0] + i4) = *(const uint2*)h;
    float4 w = *(const float4*)(Wo + i4);
    __half2 g[2] = { __floats2half2_rn(w.x, w.y), __floats2half2_rn(w.z, w.w) };
    *(uint2*)(g_W16[1] + i4) = *(const uint2*)g;
}

// ---------------- K1: fused refine-gate + x-transpose (reads x once) ----------------
// grid (NN/32, Bq), block 256. Block handles 32 node-rows x 256 feat-cols.
// NOTE: row stride 260 floats = 1040 B, 16B-aligned (fixes R13 misaligned float4).
__global__ void __launch_bounds__(256) prep_kernel(const float* __restrict__ x_ext, int use_mid,
                                                   const float* __restrict__ rg) {
    __shared__ float sx[32][260];
    __shared__ float srg[256];
    const int b  = blockIdx.y;
    const int k0 = blockIdx.x * 32;
    const int tid = threadIdx.x;
    const float* xb = (use_mid ? g_xmid : x_ext) + (size_t)b * NN * DD;

    #pragma unroll
    for (int u = 0; u < 8; ++u) {
        int e = tid + 256 * u; int r = e >> 6; int cq = e & 63;
        float4 v = *(const float4*)(xb + (size_t)(k0 + r) * DD + cq * 4);
        *(float4*)(&sx[r][cq * 4]) = v;
    }
    srg[tid] = rg[tid];
    __syncthreads();

    // gate: warp w -> rows 4w..4w+3
    {
        int warp = tid >> 5, lane = tid & 31;
        #pragma unroll
        for (int rr = 0; rr < 4; ++rr) {
            int r = warp * 4 + rr;
            float s = 0.f;
            #pragma unroll
            for (int q = 0; q < 8; ++q) s += sx[r][lane + 32 * q] * srg[lane + 32 * q];
            #pragma unroll
            for (int off = 16; off; off >>= 1) s += __shfl_xor_sync(0xffffffffu, s, off);
            if (lane == 0) g_gate[b * NN + k0 + r] = 1.f / (1.f + expf(-s));
        }
    }

    // Xt: thread d = tid writes 32 halves (the 32 k's of this block)
    {
        __half* dst = g_Xt + (size_t)b * DD * NN + (size_t)tid * NN + k0;
        #pragma unroll
        for (int w8 = 0; w8 < 4; ++w8) {
            __half2 p[4];
            #pragma unroll
            for (int q = 0; q < 4; ++q)
                p[q] = __floats2half2_rn(sx[w8 * 8 + 2 * q][tid], sx[w8 * 8 + 2 * q + 1][tid]);
            *(uint4*)(dst + w8 * 8) = *(const uint4*)p;
        }
    }
}

// ---------------- K2: fused adjacency-blend + fp16 GEMM + gcn-gate + residual ----------------
// SRC16=0 (layer 1): read fp32 dep/lat; SEL0 also streams packed fp16 to g_dep16/g_lat16.
// SRC16=1 (layer 2): read fp16 g_dep16/g_lat16.
template <int SEL, int SRC16>
__device__ __forceinline__ void adj_mainloop(
    const float* __restrict__ dep32, const float* __restrict__ lat32,
    const __half* __restrict__ depH, const __half* __restrict__ latH,
    const __half* __restrict__ Xt, const float* __restrict__ gvec,
    __half* __restrict__ dep16w, __half* __restrict__ lat16w,
    int m0, int tid, float d[4][4][4])
{
    __half* sh = (__half*)smemc;
    const int lane = tid & 31;
    const int warp = tid >> 5;
    const int wm = warp & 1, wn = warp >> 1;
    const int g = lane >> 2, t4 = lane & 3;
    const uint32_t sb = smem_u32(sh);

    // producer coords
    int arow = 0, acolq = 0, ai = 0, aj8 = 0;
    float gi = 0.f;
    float gj8[8];
    if (SEL == 0) {
        arow = tid >> 2; acolq = tid & 3;
        gi = gvec[m0 + arow];
    } else {
        ai = tid >> 4; aj8 = (tid & 15) * 8;
        #pragma unroll
        for (int q = 0; q < 8; ++q) gj8[q] = gvec[m0 + aj8 + q];
    }

    uint4 dpk, lpk;
    int stk0 = 0;

    auto loadA = [&](int k0) {
        stk0 = k0;
        if (SRC16) {
            if (SEL == 0) {
                dpk = *(const uint4*)(depH + (size_t)(m0 + arow) * NN + k0 + acolq * 8);
                lpk = *(const uint4*)(latH + (size_t)(m0 + arow) * NN + k0 + acolq * 8);
            } else {
                dpk = *(const uint4*)(depH + (size_t)(k0 + ai) * NN + m0 + aj8);
                lpk = *(const uint4*)(latH + (size_t)(k0 + ai) * NN + m0 + aj8);
            }
        } else {
            const float* dp;
            const float* lp;
            if (SEL == 0) {
                dp = dep32 + (size_t)(m0 + arow) * NN + k0 + acolq * 8;
                lp = lat32 + (size_t)(m0 + arow) * NN + k0 + acolq * 8;
            } else {
                dp = dep32 + (size_t)(k0 + ai) * NN + m0 + aj8;
                lp = lat32 + (size_t)(k0 + ai) * NN + m0 + aj8;
            }
            float4 a0 = *(const float4*)dp, a1 = *(const float4*)(dp + 4);
            __half2 hd[4] = { __floats2half2_rn(a0.x, a0.y), __floats2half2_rn(a0.z, a0.w),
                              __floats2half2_rn(a1.x, a1.y), __floats2half2_rn(a1.z, a1.w) };
            dpk = *(const uint4*)hd;
            float4 b0 = *(const float4*)lp, b1 = *(const float4*)(lp + 4);
            __half2 hl[4] = { __floats2half2_rn(b0.x, b0.y), __floats2half2_rn(b0.z, b0.w),
                              __floats2half2_rn(b1.x, b1.y), __floats2half2_rn(b1.z, b1.w) };
            lpk = *(const uint4*)hl;
        }
    };
    auto storeA = [&](int stage) {
        __half* As = sh + 2 * B_TILE_H + stage * A_TILE_H;
        const __half2* d2 = (const __half2*)&dpk;
        const __half2* l2 = (const __half2*)&lpk;
        __half2 o[4];
        #pragma unroll
        for (int q = 0; q < 4; ++q) {
            float2 df = __half22float2(d2[q]);
            float2 lf = __half22float2(l2[q]);
            float g0 = (SEL == 0) ? gi : gj8[2 * q];
            float g1 = (SEL == 0) ? gi : gj8[2 * q + 1];
            float v0 = fmaf(g0, df.x - lf.x, lf.x);
            float v1 = fmaf(g1, df.y - lf.y, lf.y);
            o[q] = __floats2half2_rn(v0, v1);
        }
        uint4 pk = *(const uint4*)o;
        if (SEL == 0) *(uint4*)(As + arow * ASTR + acolq * 8) = pk;
        else          *(uint4*)(As + ai * MSTR + aj8) = pk;
        if (!SRC16 && SEL == 0) {   // stream raw fp16 adjacencies for layer 2
            size_t off = (size_t)(m0 + arow) * NN + stk0 + acolq * 8;
            *(uint4*)(dep16w + off) = dpk;
            *(uint4*)(lat16w + off) = lpk;
        }
    };
    auto loadB = [&](int k0, int stage) {
        uint32_t dstb = sb + (uint32_t)(stage * B_TILE_H) * 2;
        #pragma unroll
        for (int u = 0; u < 2; ++u) {
            int e = tid + 512 * u; int row = e >> 2; int colq = e & 3;
            cp16(dstb + (uint32_t)(row * BSTR + colq * 8) * 2,
                 Xt + (size_t)row * NN + k0 + colq * 8);
        }
    };

    // prologue
    loadA(0); loadB(0, 0); CP_COMMIT();
    storeA(0);
    CP_WAIT0(); __syncthreads();

    const int KT = NN / 32;
    for (int kt = 0; kt < KT; ++kt) {
        int cur = kt & 1, nxt = cur ^ 1;
        bool more = (kt + 1) < KT;
        if (more) { loadA((kt + 1) * 32); loadB((kt + 1) * 32, nxt); CP_COMMIT(); }

        const __half* As = sh + 2 * B_TILE_H + cur * A_TILE_H;
        const __half* Bs = sh + cur * B_TILE_H;
        #pragma unroll
        for (int kk = 0; kk < 32; kk += 16) {
            uint32_t a[4][4], bf[4][2];
            #pragma unroll
            for (int fm = 0; fm < 4; ++fm) {
                int m = wm * 64 + fm * 16 + g;
                if (SEL == 0) {
                    a[fm][0] = *(const uint32_t*)(As + m * ASTR + kk + 2 * t4);
                    a[fm][1] = *(const uint32_t*)(As + (m + 8) * ASTR + kk + 2 * t4);
                    a[fm][2] = *(const uint32_t*)(As + m * ASTR + kk + 2 * t4 + 8);
                    a[fm][3] = *(const uint32_t*)(As + (m + 8) * ASTR + kk + 2 * t4 + 8);
                } else {
                    const uint16_t* Au = (const uint16_t*)As;
                    uint32_t k0r = (kk + 2 * t4) * MSTR, k1r = k0r + MSTR;
                    uint32_t k8r = k0r + 8 * MSTR, k9r = k8r + MSTR;
                    a[fm][0] = (uint32_t)Au[k0r + m] | ((uint32_t)Au[k1r + m] << 16);
                    a[fm][1] = (uint32_t)Au[k0r + m + 8] | ((uint32_t)Au[k1r + m + 8] << 16);
                    a[fm][2] = (uint32_t)Au[k8r + m] | ((uint32_t)Au[k9r + m] << 16);
                    a[fm][3] = (uint32_t)Au[k8r + m + 8] | ((uint32_t)Au[k9r + m + 8] << 16);
                }
            }
            #pragma unroll
            for (int fn = 0; fn < 4; ++fn) {
                int n = wn * 32 + fn * 8 + g;
                bf[fn][0] = *(const uint32_t*)(Bs + n * BSTR + kk + 2 * t4);
                bf[fn][1] = *(const uint32_t*)(Bs + n * BSTR + kk + 2 * t4 + 8);
            }
            #pragma unroll
            for (int fm = 0; fm < 4; ++fm)
                #pragma unroll
                for (int fn = 0; fn < 4; ++fn)
                    MMAH(d[fm][fn], a[fm], bf[fn]);
        }
        if (more) { storeA(nxt); CP_WAIT0(); }
        __syncthreads();
    }
}

template <int SRC16>
__global__ void __launch_bounds__(512, 1)
adj_fused_kernel(const float* __restrict__ dep, const float* __restrict__ lat,
                 const float* __restrict__ x_ext, int use_mid,
                 const float* __restrict__ Wgi, const float* __restrict__ bgi,
                 const float* __restrict__ Wgo, const float* __restrict__ bgo) {
    __shared__ float sgate[128];
    const int tid = threadIdx.x;
    const int m0  = blockIdx.x * 128;
    const int b   = blockIdx.y;
    const int sel = blockIdx.z;

    if (tid < 128) sgate[tid] = 0.f;

    const float*  dep32 = dep + (size_t)b * NN * NN;
    const float*  lat32 = lat + (size_t)b * NN * NN;
    const __half* depH  = g_dep16 + (size_t)b * NN * NN;
    const __half* latH  = g_lat16 + (size_t)b * NN * NN;
    __half* dep16w = g_dep16 + (size_t)b * NN * NN;
    __half* lat16w = g_lat16 + (size_t)b * NN * NN;
    const __half* Xt_b  = g_Xt + (size_t)b * DD * NN;
    const float* gvec   = g_gate + b * NN;

    float d[4][4][4] = {};
    if (sel == 0) adj_mainloop<0, SRC16>(dep32, lat32, depH, latH, Xt_b, gvec, dep16w, lat16w, m0, tid, d);
    else          adj_mainloop<1, SRC16>(dep32, lat32, depH, latH, Xt_b, gvec, dep16w, lat16w, m0, tid, d);

    const float* Wg = sel ? Wgo : Wgi;
    const float  bgs = sel ? bgo[0] : bgi[0];
    const float* xres = (use_mid ? g_xmid : x_ext) + (size_t)b * NN * DD;

    const int lane = tid & 31, warp = tid >> 5;
    const int wm = warp & 1, wn = warp >> 1;
    const int g = lane >> 2, c2 = (lane & 3) * 2;

    // ---- gate logit ----
    float p0[4], p1[4];
    #pragma unroll
    for (int fm = 0; fm < 4; ++fm) {
        p0[fm] = 0.f; p1[fm] = 0.f;
        #pragma unroll
        for (int fn = 0; fn < 4; ++fn) {
            int col = wn * 32 + fn * 8 + c2;
            float w0 = Wg[col], w1 = Wg[col + 1];
            p0[fm] += d[fm][fn][0] * w0 + d[fm][fn][1] * w1;
            p1[fm] += d[fm][fn][2] * w0 + d[fm][fn][3] * w1;
        }
    }
    #pragma unroll
    for (int off = 1; off <= 2; off <<= 1) {
        #pragma unroll
        for (int fm = 0; fm < 4; ++fm) {
            p0[fm] += __shfl_xor_sync(0xffffffffu, p0[fm], off);
            p1[fm] += __shfl_xor_sync(0xffffffffu, p1[fm], off);
        }
    }
    if ((lane & 3) == 0) {
        #pragma unroll
        for (int fm = 0; fm < 4; ++fm) {
            atomicAdd(&sgate[wm * 64 + fm * 16 + g],     p0[fm]);
            atomicAdd(&sgate[wm * 64 + fm * 16 + g + 8], p1[fm]);
        }
    }
    __syncthreads();

    // ---- Y = Ax*gate + bg + x -> split hi/lo fp16 planes ----
    #pragma unroll
    for (int fm = 0; fm < 4; ++fm) {
        int lr = wm * 64 + fm * 16 + g;
        float ga  = 1.f / (1.f + expf(-sgate[lr]));
        float gb2 = 1.f / (1.f + expf(-sgate[lr + 8]));
        size_t grow = (size_t)(b * NN + m0 + lr);
        const float* x0p = xres + (size_t)(m0 + lr) * DD;
        const float* x1p = x0p + 8 * DD;
        __half* yh0 = g_Yh[sel] + grow * DD;
        __half* yl0 = g_Yl[sel] + grow * DD;
        __half* yh1 = yh0 + 8 * DD;
        __half* yl1 = yl0 + 8 * DD;
        #pragma unroll
        for (int fn = 0; fn < 4; ++fn) {
            int col = wn * 32 + fn * 8 + c2;
            float2 xv0 = *(const float2*)(x0p + col);
            float2 xv1 = *(const float2*)(x1p + col);
            float o00 = d[fm][fn][0] * ga + bgs + xv0.x;
            float o01 = d[fm][fn][1] * ga + bgs + xv0.y;
            float o10 = d[fm][fn][2] * gb2 + bgs + xv1.x;
            float o11 = d[fm][fn][3] * gb2 + bgs + xv1.y;
            __half2 h0 = __floats2half2_rn(o00, o01);
            __half2 h1 = __floats2half2_rn(o10, o11);
            float2 hf0 = __half22float2(h0);
            float2 hf1 = __half22float2(h1);
            __half2 l0 = __floats2half2_rn(o00 - hf0.x, o01 - hf0.y);
            __half2 l1 = __floats2half2_rn(o10 - hf1.x, o11 - hf1.y);
            *(__half2*)(yh0 + col) = h0;  *(__half2*)(yl0 + col) = l0;
            *(__half2*)(yh1 + col) = h1;  *(__half2*)(yl1 + col) = l1;
        }
    }
}

// ---------------- K3: fc GEMM (fp16 split-A, cp.async) + LayerNorm + GELU ----------------
__global__ void __launch_bounds__(512, 1)
fc_ln_kernel(const float* __restrict__ bi, const float* __restrict__ bo,
             const float* __restrict__ gw, const float* __restrict__ bw,
             float* __restrict__ out_ext, int to_mid) {
    __half* sh   = (__half*)smemc;
    float*  hbuf = (float*)smemc;
    const int tid  = threadIdx.x;
    const int lane = tid & 31, warp = tid >> 5;
    const int wm = warp & 1, wq = warp >> 1;
    const int sel = wq >> 2, wn2 = wq & 3;
    const int g = lane >> 2, t4 = lane & 3;
    const int m0 = blockIdx.x * 128;
    const uint32_t sb = smem_u32(sh);

    const __half* base[6] = {
        g_Yh[0] + (size_t)m0 * DD, g_Yl[0] + (size_t)m0 * DD,
        g_Yh[1] + (size_t)m0 * DD, g_Yl[1] + (size_t)m0 * DD,
        g_W16[0], g_W16[1]
    };

    auto loadStage = [&](int k0, int s) {
        #pragma unroll
        for (int u = 0; u < 6; ++u) {
            int idx = tid + 512 * u;
            int t = idx >> 9, rem = idx & 511;
            int row = rem >> 2, q = rem & 3;
            cp16(sb + (uint32_t)(s * FCS + t * FCT + row * FC_AST + q * 8) * 2,
                 base[t] + (size_t)row * DD + k0 + q * 8);
        }
    };

    float d[4][4][4] = {};

    // prologue
    loadStage(0, 0); CP_COMMIT();
    CP_WAIT0(); __syncthreads();

    const int KT = DD / 32;
    for (int kt = 0; kt < KT; ++kt) {
        int cur = kt & 1, nxt = cur ^ 1;
        bool more = (kt + 1) < KT;
        if (more) { loadStage((kt + 1) * 32, nxt); CP_COMMIT(); }

        const __half* Bw = sh + cur * FCS + (4 + sel) * FCT;
        #pragma unroll
        for (int kk = 0; kk < 32; kk += 16) {
            uint32_t bf[4][2];
            #pragma unroll
            for (int fn = 0; fn < 4; ++fn) {
                int n = wn2 * 32 + fn * 8 + g;
                bf[fn][0] = *(const uint32_t*)(Bw + n * FC_AST + kk + 2 * t4);
                bf[fn][1] = *(const uint32_t*)(Bw + n * FC_AST + kk + 2 * t4 + 8);
            }
            #pragma unroll
            for (int sp = 0; sp < 2; ++sp) {
                const __half* As = sh + cur * FCS + (sel * 2 + sp) * FCT;
                uint32_t a[4][4];
                #pragma unroll
                for (int fm = 0; fm < 4; ++fm) {
                    int m = wm * 64 + fm * 16 + g;
                    a[fm][0] = *(const uint32_t*)(As + m * FC_AST + kk + 2 * t4);
                    a[fm][1] = *(const uint32_t*)(As + (m + 8) * FC_AST + kk + 2 * t4);
                    a[fm][2] = *(const uint32_t*)(As + m * FC_AST + kk + 2 * t4 + 8);
                    a[fm][3] = *(const uint32_t*)(As + (m + 8) * FC_AST + kk + 2 * t4 + 8);
                }
                #pragma unroll
                for (int fm = 0; fm < 4; ++fm)
                    #pragma unroll
                    for (int fn = 0; fn < 4; ++fn)
                        MMAH(d[fm][fn], a[fm], bf[fn]);
            }
        }
        if (more) CP_WAIT0();
        __syncthreads();
    }

    // ---- write h into smem hbuf (stride 260) ----
    const float* bias = sel ? bo : bi;
    const int c2 = t4 * 2;
    #pragma unroll
    for (int fm = 0; fm < 4; ++fm) {
        int lr = wm * 64 + fm * 16 + g;
        #pragma unroll
        for (int fn = 0; fn < 4; ++fn) {
            int cl = wn2 * 32 + fn * 8 + c2;
            int colg = sel * 128 + cl;
            float b0 = 2.f * bias[cl], b1 = 2.f * bias[cl + 1];
            hbuf[lr * 260 + colg]           = d[fm][fn][0] + b0;
            hbuf[lr * 260 + colg + 1]       = d[fm][fn][1] + b1;
            hbuf[(lr + 8) * 260 + colg]     = d[fm][fn][2] + b0;
            hbuf[(lr + 8) * 260 + colg + 1] = d[fm][fn][3] + b1;
        }
    }
    __syncthreads();

    // ---- LayerNorm(256) + exact GELU, 4 threads per row ----
    {
        int row = tid >> 2, p = tid & 3;
        float s = 0.f, s2 = 0.f;
        #pragma unroll
        for (int j = 0; j < 16; ++j) {
            float4 v = *(const float4*)(hbuf + row * 260 + p * 4 + 16 * j);
            s += v.x + v.y + v.z + v.w;
            s2 += v.x * v.x + v.y * v.y + v.z * v.z + v.w * v.w;
        }
        #pragma unroll
        for (int off = 1; off <= 2; off <<= 1) {
            s  += __shfl_xor_sync(0xffffffffu, s,  off);
            s2 += __shfl_xor_sync(0xffffffffu, s2, off);
        }
        float mu  = s * (1.f / DD);
        float var = s2 * (1.f / DD) - mu * mu;
        float rr  = rsqrtf(var + 1e-5f);
        float* outp = (to_mid ? g_xmid : out_ext) + (size_t)(m0 + row) * DD;
        #pragma unroll
        for (int j = 0; j < 16; ++j) {
            int col = p * 4 + 16 * j;
            float4 v = *(const float4*)(hbuf + row * 260 + col);
            float4 o;
            float hn;
            hn = (v.x - mu) * rr * gw[col]     + bw[col];
            o.x = 0.5f * hn * (1.f + erff(hn * 0.70710678118654752f));
            hn = (v.y - mu) * rr * gw[col + 1] + bw[col + 1];
            o.y = 0.5f * hn * (1.f + erff(hn * 0.70710678118654752f));
            hn = (v.z - mu) * rr * gw[col + 2] + bw[col + 2];
            o.z = 0.5f * hn * (1.f + erff(hn * 0.70710678118654752f));
            hn = (v.w - mu) * rr * gw[col + 3] + bw[col + 3];
            o.w = 0.5f * hn * (1.f + erff(hn * 0.70710678118654752f));
            *(float4*)(outp + col) = o;
        }
    }
}

// ---------------- host launcher ----------------
extern "C" void kernel_launch(void* const* d_in, const int* in_sizes, int n_in,
                              void* d_out, int out_size) {
    (void)in_sizes; (void)n_in; (void)out_size;
    const float* x0  = (const float*)d_in[0];
    const float* lat = (const float*)d_in[1];
    const float* dep = (const float*)d_in[2];
    const float* rg  = (const float*)d_in[3];
    const float* Wgi = (const float*)d_in[4];
    const float* bgi = (const float*)d_in[5];
    const float* Wgo = (const float*)d_in[6];
    const float* bgo = (const float*)d_in[7];
    const float* Wi  = (const float*)d_in[8];
    const float* bi  = (const float*)d_in[9];
    const float* Wo  = (const float*)d_in[10];
    const float* bo  = (const float*)d_in[11];
    const float* lng = (const float*)d_in[12];
    const float* lnb = (const float*)d_in[13];
    float* out = (float*)d_out;

    cudaFuncSetAttribute(adj_fused_kernel<0>, cudaFuncAttributeMaxDynamicSharedMemorySize, ADJ_SMEM);
    cudaFuncSetAttribute(adj_fused_kernel<1>, cudaFuncAttributeMaxDynamicSharedMemorySize, ADJ_SMEM);
    cudaFuncSetAttribute(fc_ln_kernel,        cudaFuncAttributeMaxDynamicSharedMemorySize, FC_SMEM);

    for (int l = 0; l < LL; l++) {
        int use_mid = (l != 0);
        int to_mid  = (l != LL - 1);

        dim3 gP(NN / 32, Bq);
        prep_kernel<<<gP, 256>>>(x0, use_mid, rg + l * DD);

        w16_kernel<<<HH * DD / (256 * 4), 256>>>(Wi + (size_t)l * HH * DD,
                                                 Wo + (size_t)l * HH * DD);

        dim3 gM(NN / 128, Bq, 2);
        if (l == 0)
            adj_fused_kernel<0><<<gM, 512, ADJ_SMEM>>>(dep, lat, x0, use_mid,
                                                       Wgi + l * DD, bgi + l,
                                                       Wgo + l * DD, bgo + l);
        else
            adj_fused_kernel<1><<<gM, 512, ADJ_SMEM>>>(dep, lat, x0, use_mid,
                                                       Wgi + l * DD, bgi + l,
                                                       Wgo + l * DD, bgo + l);

        fc_ln_kernel<<<(Bq * NN) / 128, 512, FC_SMEM>>>(
            bi + l * HH, bo + l * HH,
            lng + l * 2 * HH, lnb + l * 2 * HH,
            out, to_mid);
    }
}

// round 15
// speedup vs baseline: 1.0708x; 1.0708x over previous
#include <cuda_runtime.h>
#include <cuda_fp16.h>
#include <math.h>
#include <stdint.h>

#define Bq 16
#define NN 1024
#define DD 256
#define HH 128
#define LL 2

// ---------------- scratch (device globals; no allocation) ----------------
__device__ __align__(128) float  g_gate[Bq * NN];
__device__ __align__(128) __half g_Xt  [Bq * DD * NN];           // x^T [b,d,k] fp16
__device__ __align__(128) __half g_Yh[2][(size_t)Bq * NN * DD];  // Y hi plane per sel
__device__ __align__(128) __half g_Yl[2][(size_t)Bq * NN * DD];  // Y lo plane per sel
__device__ __align__(128) __half g_W16[2][HH * DD];
__device__ __align__(128) float  g_xmid[Bq * NN * DD];

// ---------------- helpers ----------------
__device__ __forceinline__ uint32_t smem_u32(const void* p) {
    uint32_t a;
    asm("{ .reg .u64 t; cvta.to.shared.u64 t, %1; cvt.u32.u64 %0, t; }" : "=r"(a) : "l"(p));
    return a;
}
__device__ __forceinline__ void cp16(uint32_t dst, const void* src) {
    asm volatile("cp.async.cg.shared.global [%0], [%1], 16;" :: "r"(dst), "l"(src) : "memory");
}
#define CP_COMMIT() asm volatile("cp.async.commit_group;" ::: "memory")
#define CP_WAIT0()  asm volatile("cp.async.wait_group 0;" ::: "memory")

#define MMAH(D, A, B) \
    asm volatile("mma.sync.aligned.m16n8k16.row.col.f32.f16.f16.f32 " \
        "{%0,%1,%2,%3}, {%4,%5,%6,%7}, {%8,%9}, {%0,%1,%2,%3};" \
        : "+f"((D)[0]), "+f"((D)[1]), "+f"((D)[2]), "+f"((D)[3]) \
        : "r"((A)[0]), "r"((A)[1]), "r"((A)[2]), "r"((A)[3]), \
          "r"((B)[0]), "r"((B)[1]))

// adjacency kernel smem geometry (halves). CTA tile 64 rows x 256 cols.
#define BSTR 40
#define ASTR 40
#define MSTR 72                          // SEL1 k-major stride (64 m + pad)
#define B_TILE_H (256 * BSTR)            // 10240 halves per B stage
#define A_TILE_H 2560                    // 64*40 = 2560 >= 32*72 = 2304
#define ADJ_SMEM ((2 * B_TILE_H + 2 * A_TILE_H) * 2)   // 51200 bytes

// fc kernel smem
#define FC_AST 40
#define FCT (128 * FC_AST)               // 5120 halves per tile
#define FCS (6 * FCT)                    // Yhi0,Ylo0,Yhi1,Ylo1,W0,W1
#define FC_SMEM (128 * 260 * 4)          // 133120 bytes

extern __shared__ char smemc[];

// ---------------- K0: W -> fp16 (per layer) ----------------
__global__ void w16_kernel(const float* __restrict__ Wi, const float* __restrict__ Wo) {
    int i4 = (blockIdx.x * 256 + threadIdx.x) * 4;
    if (i4 >= HH * DD) return;
    float4 v = *(const float4*)(Wi + i4);
    __half2 h[2] = { __floats2half2_rn(v.x, v.y), __floats2half2_rn(v.z, v.w) };
    *(uint2*)(g_W16[0] + i4) = *(const uint2*)h;
    float4 w = *(const float4*)(Wo + i4);
    __half2 g[2] = { __floats2half2_rn(w.x, w.y), __floats2half2_rn(w.z, w.w) };
    *(uint2*)(g_W16[1] + i4) = *(const uint2*)g;
}

// ---------------- K1: fused refine-gate + x-transpose (reads x once) ----------------
__global__ void __launch_bounds__(256) prep_kernel(const float* __restrict__ x_ext, int use_mid,
                                                   const float* __restrict__ rg) {
    __shared__ float sx[32][260];
    __shared__ float srg[256];
    const int b  = blockIdx.y;
    const int k0 = blockIdx.x * 32;
    const int tid = threadIdx.x;
    const float* xb = (use_mid ? g_xmid : x_ext) + (size_t)b * NN * DD;

    #pragma unroll
    for (int u = 0; u < 8; ++u) {
        int e = tid + 256 * u; int r = e >> 6; int cq = e & 63;
        float4 v = *(const float4*)(xb + (size_t)(k0 + r) * DD + cq * 4);
        *(float4*)(&sx[r][cq * 4]) = v;
    }
    srg[tid] = rg[tid];
    __syncthreads();

    {
        int warp = tid >> 5, lane = tid & 31;
        #pragma unroll
        for (int rr = 0; rr < 4; ++rr) {
            int r = warp * 4 + rr;
            float s = 0.f;
            #pragma unroll
            for (int q = 0; q < 8; ++q) s += sx[r][lane + 32 * q] * srg[lane + 32 * q];
            #pragma unroll
            for (int off = 16; off; off >>= 1) s += __shfl_xor_sync(0xffffffffu, s, off);
            if (lane == 0) g_gate[b * NN + k0 + r] = 1.f / (1.f + expf(-s));
        }
    }
    {
        __half* dst = g_Xt + (size_t)b * DD * NN + (size_t)tid * NN + k0;
        #pragma unroll
        for (int w8 = 0; w8 < 4; ++w8) {
            __half2 p[4];
            #pragma unroll
            for (int q = 0; q < 4; ++q)
                p[q] = __floats2half2_rn(sx[w8 * 8 + 2 * q][tid], sx[w8 * 8 + 2 * q + 1][tid]);
            *(uint4*)(dst + w8 * 8) = *(const uint4*)p;
        }
    }
}

// ---------------- K2: fused adjacency-blend + fp16 GEMM + gcn-gate + residual ----------------
// CTA: 64 rows x 256 cols, 256 threads (8 warps, warp tile 32x64), 2 CTAs/SM.
template <int SEL>
__device__ __forceinline__ void adj_mainloop(
    const float* __restrict__ dep32, const float* __restrict__ lat32,
    const __half* __restrict__ Xt, const float* __restrict__ gvec,
    int m0, int tid, float d[2][8][4])
{
    __half* sh = (__half*)smemc;
    const int lane = tid & 31;
    const int warp = tid >> 5;
    const int wm = warp & 1, wn = warp >> 1;
    const int g = lane >> 2, t4 = lane & 3;
    const uint32_t sb = smem_u32(sh);

    // producer coords
    int arow = 0, acolq = 0, ai = 0, aj8 = 0;
    float gi = 0.f;
    float gj8[8];
    if (SEL == 0) {
        arow = tid >> 2; acolq = tid & 3;          // 64 rows x (4 quads of 8 k)
        gi = gvec[m0 + arow];
    } else {
        ai = tid >> 3; aj8 = (tid & 7) * 8;        // 32 k x (8 blocks of 8 m)
        #pragma unroll
        for (int q = 0; q < 8; ++q) gj8[q] = gvec[m0 + aj8 + q];
    }

    float4 dv0, dv1, lv0, lv1;

    auto loadA = [&](int k0) {
        const float* dp;
        const float* lp;
        if (SEL == 0) {
            dp = dep32 + (size_t)(m0 + arow) * NN + k0 + acolq * 8;
            lp = lat32 + (size_t)(m0 + arow) * NN + k0 + acolq * 8;
        } else {
            dp = dep32 + (size_t)(k0 + ai) * NN + m0 + aj8;
            lp = lat32 + (size_t)(k0 + ai) * NN + m0 + aj8;
        }
        dv0 = *(const float4*)dp;  dv1 = *(const float4*)(dp + 4);
        lv0 = *(const float4*)lp;  lv1 = *(const float4*)(lp + 4);
    };
    auto storeA = [&](int stage) {
        __half* As = sh + 2 * B_TILE_H + stage * A_TILE_H;
        float v[8];
        if (SEL == 0) {
            v[0] = fmaf(gi, dv0.x - lv0.x, lv0.x); v[1] = fmaf(gi, dv0.y - lv0.y, lv0.y);
            v[2] = fmaf(gi, dv0.z - lv0.z, lv0.z); v[3] = fmaf(gi, dv0.w - lv0.w, lv0.w);
            v[4] = fmaf(gi, dv1.x - lv1.x, lv1.x); v[5] = fmaf(gi, dv1.y - lv1.y, lv1.y);
            v[6] = fmaf(gi, dv1.z - lv1.z, lv1.z); v[7] = fmaf(gi, dv1.w - lv1.w, lv1.w);
        } else {
            v[0] = fmaf(gj8[0], dv0.x - lv0.x, lv0.x); v[1] = fmaf(gj8[1], dv0.y - lv0.y, lv0.y);
            v[2] = fmaf(gj8[2], dv0.z - lv0.z, lv0.z); v[3] = fmaf(gj8[3], dv0.w - lv0.w, lv0.w);
            v[4] = fmaf(gj8[4], dv1.x - lv1.x, lv1.x); v[5] = fmaf(gj8[5], dv1.y - lv1.y, lv1.y);
            v[6] = fmaf(gj8[6], dv1.z - lv1.z, lv1.z); v[7] = fmaf(gj8[7], dv1.w - lv1.w, lv1.w);
        }
        __half2 h2[4];
        #pragma unroll
        for (int q = 0; q < 4; ++q) h2[q] = __floats2half2_rn(v[2 * q], v[2 * q + 1]);
        uint4 pk = *(const uint4*)h2;
        if (SEL == 0) *(uint4*)(As + arow * ASTR + acolq * 8) = pk;
        else          *(uint4*)(As + ai * MSTR + aj8) = pk;
    };
    auto loadB = [&](int k0, int stage) {
        uint32_t dstb = sb + (uint32_t)(stage * B_TILE_H) * 2;
        #pragma unroll
        for (int u = 0; u < 4; ++u) {
            int e = tid + 256 * u; int row = e >> 2; int colq = e & 3;
            cp16(dstb + (uint32_t)(row * BSTR + colq * 8) * 2,
                 Xt + (size_t)row * NN + k0 + colq * 8);
        }
    };

    // prologue
    loadA(0); loadB(0, 0); CP_COMMIT();
    storeA(0);
    CP_WAIT0(); __syncthreads();

    const int KT = NN / 32;
    for (int kt = 0; kt < KT; ++kt) {
        int cur = kt & 1, nxt = cur ^ 1;
        bool more = (kt + 1) < KT;
        if (more) { loadA((kt + 1) * 32); loadB((kt + 1) * 32, nxt); CP_COMMIT(); }

        const __half* As = sh + 2 * B_TILE_H + cur * A_TILE_H;
        const __half* Bs = sh + cur * B_TILE_H;
        #pragma unroll
        for (int kk = 0; kk < 32; kk += 16) {
            uint32_t a[2][4], bf[8][2];
            #pragma unroll
            for (int fm = 0; fm < 2; ++fm) {
                int m = wm * 32 + fm * 16 + g;
                if (SEL == 0) {
                    a[fm][0] = *(const uint32_t*)(As + m * ASTR + kk + 2 * t4);
                    a[fm][1] = *(const uint32_t*)(As + (m + 8) * ASTR + kk + 2 * t4);
                    a[fm][2] = *(const uint32_t*)(As + m * ASTR + kk + 2 * t4 + 8);
                    a[fm][3] = *(const uint32_t*)(As + (m + 8) * ASTR + kk + 2 * t4 + 8);
                } else {
                    const uint16_t* Au = (const uint16_t*)As;
                    uint32_t k0r = (kk + 2 * t4) * MSTR, k1r = k0r + MSTR;
                    uint32_t k8r = k0r + 8 * MSTR, k9r = k8r + MSTR;
                    a[fm][0] = (uint32_t)Au[k0r + m] | ((uint32_t)Au[k1r + m] << 16);
                    a[fm][1] = (uint32_t)Au[k0r + m + 8] | ((uint32_t)Au[k1r + m + 8] << 16);
                    a[fm][2] = (uint32_t)Au[k8r + m] | ((uint32_t)Au[k9r + m] << 16);
                    a[fm][3] = (uint32_t)Au[k8r + m + 8] | ((uint32_t)Au[k9r + m + 8] << 16);
                }
            }
            #pragma unroll
            for (int fn = 0; fn < 8; ++fn) {
                int n = wn * 64 + fn * 8 + g;
                bf[fn][0] = *(const uint32_t*)(Bs + n * BSTR + kk + 2 * t4);
                bf[fn][1] = *(const uint32_t*)(Bs + n * BSTR + kk + 2 * t4 + 8);
            }
            #pragma unroll
            for (int fm = 0; fm < 2; ++fm)
                #pragma unroll
                for (int fn = 0; fn < 8; ++fn)
                    MMAH(d[fm][fn], a[fm], bf[fn]);
        }
        if (more) { storeA(nxt); CP_WAIT0(); }
        __syncthreads();
    }
}

__global__ void __launch_bounds__(256, 2)
adj_fused_kernel(const float* __restrict__ dep, const float* __restrict__ lat,
                 const float* __restrict__ x_ext, int use_mid,
                 const float* __restrict__ Wgi, const float* __restrict__ bgi,
                 const float* __restrict__ Wgo, const float* __restrict__ bgo) {
    __shared__ float sgate[64];
    const int tid = threadIdx.x;
    const int m0  = blockIdx.x * 64;
    const int b   = blockIdx.y;
    const int sel = blockIdx.z;

    if (tid < 64) sgate[tid] = 0.f;

    const float* dep32 = dep + (size_t)b * NN * NN;
    const float* lat32 = lat + (size_t)b * NN * NN;
    const __half* Xt_b = g_Xt + (size_t)b * DD * NN;
    const float* gvec  = g_gate + b * NN;

    float d[2][8][4] = {};
    if (sel == 0) adj_mainloop<0>(dep32, lat32, Xt_b, gvec, m0, tid, d);
    else          adj_mainloop<1>(dep32, lat32, Xt_b, gvec, m0, tid, d);

    const float* Wg = sel ? Wgo : Wgi;
    const float  bgs = sel ? bgo[0] : bgi[0];
    const float* xres = (use_mid ? g_xmid : x_ext) + (size_t)b * NN * DD;

    const int lane = tid & 31, warp = tid >> 5;
    const int wm = warp & 1, wn = warp >> 1;
    const int g = lane >> 2, c2 = (lane & 3) * 2;

    // ---- gate logit ----
    float p0[2], p1[2];
    #pragma unroll
    for (int fm = 0; fm < 2; ++fm) {
        p0[fm] = 0.f; p1[fm] = 0.f;
        #pragma unroll
        for (int fn = 0; fn < 8; ++fn) {
            int col = wn * 64 + fn * 8 + c2;
            float w0 = Wg[col], w1 = Wg[col + 1];
            p0[fm] += d[fm][fn][0] * w0 + d[fm][fn][1] * w1;
            p1[fm] += d[fm][fn][2] * w0 + d[fm][fn][3] * w1;
        }
    }
    #pragma unroll
    for (int off = 1; off <= 2; off <<= 1) {
        #pragma unroll
        for (int fm = 0; fm < 2; ++fm) {
            p0[fm] += __shfl_xor_sync(0xffffffffu, p0[fm], off);
            p1[fm] += __shfl_xor_sync(0xffffffffu, p1[fm], off);
        }
    }
    if ((lane & 3) == 0) {
        #pragma unroll
        for (int fm = 0; fm < 2; ++fm) {
            atomicAdd(&sgate[wm * 32 + fm * 16 + g],     p0[fm]);
            atomicAdd(&sgate[wm * 32 + fm * 16 + g + 8], p1[fm]);
        }
    }
    __syncthreads();

    // ---- Y = Ax*gate + bg + x -> split hi/lo fp16 planes ----
    #pragma unroll
    for (int fm = 0; fm < 2; ++fm) {
        int lr = wm * 32 + fm * 16 + g;
        float ga  = 1.f / (1.f + expf(-sgate[lr]));
        float gb2 = 1.f / (1.f + expf(-sgate[lr + 8]));
        size_t grow = (size_t)(b * NN + m0 + lr);
        const float* x0p = xres + (size_t)(m0 + lr) * DD;
        const float* x1p = x0p + 8 * DD;
        __half* yh0 = g_Yh[sel] + grow * DD;
        __half* yl0 = g_Yl[sel] + grow * DD;
        __half* yh1 = yh0 + 8 * DD;
        __half* yl1 = yl0 + 8 * DD;
        #pragma unroll
        for (int fn = 0; fn < 8; ++fn) {
            int col = wn * 64 + fn * 8 + c2;
            float2 xv0 = *(const float2*)(x0p + col);
            float2 xv1 = *(const float2*)(x1p + col);
            float o00 = d[fm][fn][0] * ga + bgs + xv0.x;
            float o01 = d[fm][fn][1] * ga + bgs + xv0.y;
            float o10 = d[fm][fn][2] * gb2 + bgs + xv1.x;
            float o11 = d[fm][fn][3] * gb2 + bgs + xv1.y;
            __half2 h0 = __floats2half2_rn(o00, o01);
            __half2 h1 = __floats2half2_rn(o10, o11);
            float2 hf0 = __half22float2(h0);
            float2 hf1 = __half22float2(h1);
            __half2 l0 = __floats2half2_rn(o00 - hf0.x, o01 - hf0.y);
            __half2 l1 = __floats2half2_rn(o10 - hf1.x, o11 - hf1.y);
            *(__half2*)(yh0 + col) = h0;  *(__half2*)(yl0 + col) = l0;
            *(__half2*)(yh1 + col) = h1;  *(__half2*)(yl1 + col) = l1;
        }
    }
}

// ---------------- K3: fc GEMM (fp16 split-A, cp.async) + LayerNorm + GELU ----------------
__global__ void __launch_bounds__(512, 1)
fc_ln_kernel(const float* __restrict__ bi, const float* __restrict__ bo,
             const float* __restrict__ gw, const float* __restrict__ bw,
             float* __restrict__ out_ext, int to_mid) {
    __half* sh   = (__half*)smemc;
    float*  hbuf = (float*)smemc;
    const int tid  = threadIdx.x;
    const int lane = tid & 31, warp = tid >> 5;
    const int wm = warp & 1, wq = warp >> 1;
    const int sel = wq >> 2, wn2 = wq & 3;
    const int g = lane >> 2, t4 = lane & 3;
    const int m0 = blockIdx.x * 128;
    const uint32_t sb = smem_u32(sh);

    const __half* base[6] = {
        g_Yh[0] + (size_t)m0 * DD, g_Yl[0] + (size_t)m0 * DD,
        g_Yh[1] + (size_t)m0 * DD, g_Yl[1] + (size_t)m0 * DD,
        g_W16[0], g_W16[1]
    };

    auto loadStage = [&](int k0, int s) {
        #pragma unroll
        for (int u = 0; u < 6; ++u) {
            int idx = tid + 512 * u;
            int t = idx >> 9, rem = idx & 511;
            int row = rem >> 2, q = rem & 3;
            cp16(sb + (uint32_t)(s * FCS + t * FCT + row * FC_AST + q * 8) * 2,
                 base[t] + (size_t)row * DD + k0 + q * 8);
        }
    };

    float d[4][4][4] = {};

    loadStage(0, 0); CP_COMMIT();
    CP_WAIT0(); __syncthreads();

    const int KT = DD / 32;
    for (int kt = 0; kt < KT; ++kt) {
        int cur = kt & 1, nxt = cur ^ 1;
        bool more = (kt + 1) < KT;
        if (more) { loadStage((kt + 1) * 32, nxt); CP_COMMIT(); }

        const __half* Bw = sh + cur * FCS + (4 + sel) * FCT;
        #pragma unroll
        for (int kk = 0; kk < 32; kk += 16) {
            uint32_t bf[4][2];
            #pragma unroll
            for (int fn = 0; fn < 4; ++fn) {
                int n = wn2 * 32 + fn * 8 + g;
                bf[fn][0] = *(const uint32_t*)(Bw + n * FC_AST + kk + 2 * t4);
                bf[fn][1] = *(const uint32_t*)(Bw + n * FC_AST + kk + 2 * t4 + 8);
            }
            #pragma unroll
            for (int sp = 0; sp < 2; ++sp) {
                const __half* As = sh + cur * FCS + (sel * 2 + sp) * FCT;
                uint32_t a[4][4];
                #pragma unroll
                for (int fm = 0; fm < 4; ++fm) {
                    int m = wm * 64 + fm * 16 + g;
                    a[fm][0] = *(const uint32_t*)(As + m * FC_AST + kk + 2 * t4);
                    a[fm][1] = *(const uint32_t*)(As + (m + 8) * FC_AST + kk + 2 * t4);
                    a[fm][2] = *(const uint32_t*)(As + m * FC_AST + kk + 2 * t4 + 8);
                    a[fm][3] = *(const uint32_t*)(As + (m + 8) * FC_AST + kk + 2 * t4 + 8);
                }
                #pragma unroll
                for (int fm = 0; fm < 4; ++fm)
                    #pragma unroll
                    for (int fn = 0; fn < 4; ++fn)
                        MMAH(d[fm][fn], a[fm], bf[fn]);
            }
        }
        if (more) CP_WAIT0();
        __syncthreads();
    }

    // ---- write h into smem hbuf (stride 260) ----
    const float* bias = sel ? bo : bi;
    const int c2 = t4 * 2;
    #pragma unroll
    for (int fm = 0; fm < 4; ++fm) {
        int lr = wm * 64 + fm * 16 + g;
        #pragma unroll
        for (int fn = 0; fn < 4; ++fn) {
            int cl = wn2 * 32 + fn * 8 + c2;
            int colg = sel * 128 + cl;
            float b0 = 2.f * bias[cl], b1 = 2.f * bias[cl + 1];
            hbuf[lr * 260 + colg]           = d[fm][fn][0] + b0;
            hbuf[lr * 260 + colg + 1]       = d[fm][fn][1] + b1;
            hbuf[(lr + 8) * 260 + colg]     = d[fm][fn][2] + b0;
            hbuf[(lr + 8) * 260 + colg + 1] = d[fm][fn][3] + b1;
        }
    }
    __syncthreads();

    // ---- LayerNorm(256) + exact GELU, 4 threads per row ----
    {
        int row = tid >> 2, p = tid & 3;
        float s = 0.f, s2 = 0.f;
        #pragma unroll
        for (int j = 0; j < 16; ++j) {
            float4 v = *(const float4*)(hbuf + row * 260 + p * 4 + 16 * j);
            s += v.x + v.y + v.z + v.w;
            s2 += v.x * v.x + v.y * v.y + v.z * v.z + v.w * v.w;
        }
        #pragma unroll
        for (int off = 1; off <= 2; off <<= 1) {
            s  += __shfl_xor_sync(0xffffffffu, s,  off);
            s2 += __shfl_xor_sync(0xffffffffu, s2, off);
        }
        float mu  = s * (1.f / DD);
        float var = s2 * (1.f / DD) - mu * mu;
        float rr  = rsqrtf(var + 1e-5f);
        float* outp = (to_mid ? g_xmid : out_ext) + (size_t)(m0 + row) * DD;
        #pragma unroll
        for (int j = 0; j < 16; ++j) {
            int col = p * 4 + 16 * j;
            float4 v = *(const float4*)(hbuf + row * 260 + col);
            float4 o;
            float hn;
            hn = (v.x - mu) * rr * gw[col]     + bw[col];
            o.x = 0.5f * hn * (1.f + erff(hn * 0.70710678118654752f));
            hn = (v.y - mu) * rr * gw[col + 1] + bw[col + 1];
            o.y = 0.5f * hn * (1.f + erff(hn * 0.70710678118654752f));
            hn = (v.z - mu) * rr * gw[col + 2] + bw[col + 2];
            o.z = 0.5f * hn * (1.f + erff(hn * 0.70710678118654752f));
            hn = (v.w - mu) * rr * gw[col + 3] + bw[col + 3];
            o.w = 0.5f * hn * (1.f + erff(hn * 0.70710678118654752f));
            *(float4*)(outp + col) = o;
        }
    }
}

// ---------------- host launcher ----------------
extern "C" void kernel_launch(void* const* d_in, const int* in_sizes, int n_in,
                              void* d_out, int out_size) {
    (void)in_sizes; (void)n_in; (void)out_size;
    const float* x0  = (const float*)d_in[0];
    const float* lat = (const float*)d_in[1];
    const float* dep = (const float*)d_in[2];
    const float* rg  = (const float*)d_in[3];
    const float* Wgi = (const float*)d_in[4];
    const float* bgi = (const float*)d_in[5];
    const float* Wgo = (const float*)d_in[6];
    const float* bgo = (const float*)d_in[7];
    const float* Wi  = (const float*)d_in[8];
    const float* bi  = (const float*)d_in[9];
    const float* Wo  = (const float*)d_in[10];
    const float* bo  = (const float*)d_in[11];
    const float* lng = (const float*)d_in[12];
    const float* lnb = (const float*)d_in[13];
    float* out = (float*)d_out;

    cudaFuncSetAttribute(adj_fused_kernel, cudaFuncAttributeMaxDynamicSharedMemorySize, ADJ_SMEM);
    cudaFuncSetAttribute(fc_ln_kernel,     cudaFuncAttributeMaxDynamicSharedMemorySize, FC_SMEM);

    for (int l = 0; l < LL; l++) {
        int use_mid = (l != 0);
        int to_mid  = (l != LL - 1);

        dim3 gP(NN / 32, Bq);
        prep_kernel<<<gP, 256>>>(x0, use_mid, rg + l * DD);

        w16_kernel<<<HH * DD / (256 * 4), 256>>>(Wi + (size_t)l * HH * DD,
                                                 Wo + (size_t)l * HH * DD);

        dim3 gM(NN / 64, Bq, 2);
        adj_fused_kernel<<<gM, 256, ADJ_SMEM>>>(dep, lat, x0, use_mid,
                                                Wgi + l * DD, bgi + l,
                                                Wgo + l * DD, bgo + l);

        fc_ln_kernel<<<(Bq * NN) / 128, 512, FC_SMEM>>>(
            bi + l * HH, bo + l * HH,
            lng + l * 2 * HH, lnb + l * 2 * HH,
            out, to_mid);
    }
}

// round 16
// speedup vs baseline: 1.1581x; 1.0815x over previous
#include <cuda_runtime.h>
#include <cuda_fp16.h>
#include <math.h>
#include <stdint.h>

#define Bq 16
#define NN 1024
#define DD 256
#define HH 128
#define LL 2

// ---------------- scratch (device globals; no allocation) ----------------
__device__ __align__(128) float  g_gate[Bq * NN];
__device__ __align__(128) __half g_Xt  [Bq * DD * NN];           // x^T [b,d,k] fp16
__device__ __align__(128) __half g_Yh[2][(size_t)Bq * NN * DD];  // Y fp16 per sel
__device__ __align__(128) __half g_W16[2][HH * DD];
__device__ __align__(128) float  g_xmid[Bq * NN * DD];

// ---------------- helpers ----------------
__device__ __forceinline__ uint32_t smem_u32(const void* p) {
    uint32_t a;
    asm("{ .reg .u64 t; cvta.to.shared.u64 t, %1; cvt.u32.u64 %0, t; }" : "=r"(a) : "l"(p));
    return a;
}
__device__ __forceinline__ void cp16(uint32_t dst, const void* src) {
    asm volatile("cp.async.cg.shared.global [%0], [%1], 16;" :: "r"(dst), "l"(src) : "memory");
}
#define CP_COMMIT() asm volatile("cp.async.commit_group;" ::: "memory")
#define CP_WAIT0()  asm volatile("cp.async.wait_group 0;" ::: "memory")

#define MMAH(D, A, B) \
    asm volatile("mma.sync.aligned.m16n8k16.row.col.f32.f16.f16.f32 " \
        "{%0,%1,%2,%3}, {%4,%5,%6,%7}, {%8,%9}, {%0,%1,%2,%3};" \
        : "+f"((D)[0]), "+f"((D)[1]), "+f"((D)[2]), "+f"((D)[3]) \
        : "r"((A)[0]), "r"((A)[1]), "r"((A)[2]), "r"((A)[3]), \
          "r"((B)[0]), "r"((B)[1]))

// adjacency kernel smem geometry (halves). CTA tile 64 rows x 256 cols.
#define BSTR 40
#define ASTR 40
#define MSTR 72                          // SEL1 k-major stride (64 m + pad)
#define B_TILE_H (256 * BSTR)            // 10240 halves per B stage
#define A_TILE_H 2560                    // 64*40 >= 32*72
#define ADJ_SMEM ((2 * B_TILE_H + 2 * A_TILE_H) * 2)   // 51200 bytes

// fc kernel smem
#define FC_AST 40
#define FCT (128 * FC_AST)               // 5120 halves per tile
#define FCS (4 * FCT)                    // tiles per stage: Y0, Y1, W0, W1
#define FC_SMEM (128 * 260 * 4)          // 133120 bytes (hbuf dominates; 2*FCS*2=81920 fits)

extern __shared__ char smemc[];

// ---------------- K0: W -> fp16 (per layer) ----------------
__global__ void w16_kernel(const float* __restrict__ Wi, const float* __restrict__ Wo) {
    int i4 = (blockIdx.x * 256 + threadIdx.x) * 4;
    if (i4 >= HH * DD) return;
    float4 v = *(const float4*)(Wi + i4);
    __half2 h[2] = { __floats2half2_rn(v.x, v.y), __floats2half2_rn(v.z, v.w) };
    *(uint2*)(g_W16[0] + i4) = *(const uint2*)h;
    float4 w = *(const float4*)(Wo + i4);
    __half2 g[2] = { __floats2half2_rn(w.x, w.y), __floats2half2_rn(w.z, w.w) };
    *(uint2*)(g_W16[1] + i4) = *(const uint2*)g;
}

// ---------------- K1: fused refine-gate + x-transpose (reads x once) ----------------
__global__ void __launch_bounds__(256) prep_kernel(const float* __restrict__ x_ext, int use_mid,
                                                   const float* __restrict__ rg) {
    __shared__ float sx[32][260];
    __shared__ float srg[256];
    const int b  = blockIdx.y;
    const int k0 = blockIdx.x * 32;
    const int tid = threadIdx.x;
    const float* xb = (use_mid ? g_xmid : x_ext) + (size_t)b * NN * DD;

    #pragma unroll
    for (int u = 0; u < 8; ++u) {
        int e = tid + 256 * u; int r = e >> 6; int cq = e & 63;
        float4 v = *(const float4*)(xb + (size_t)(k0 + r) * DD + cq * 4);
        *(float4*)(&sx[r][cq * 4]) = v;
    }
    srg[tid] = rg[tid];
    __syncthreads();

    {
        int warp = tid >> 5, lane = tid & 31;
        #pragma unroll
        for (int rr = 0; rr < 4; ++rr) {
            int r = warp * 4 + rr;
            float s = 0.f;
            #pragma unroll
            for (int q = 0; q < 8; ++q) s += sx[r][lane + 32 * q] * srg[lane + 32 * q];
            #pragma unroll
            for (int off = 16; off; off >>= 1) s += __shfl_xor_sync(0xffffffffu, s, off);
            if (lane == 0) g_gate[b * NN + k0 + r] = 1.f / (1.f + expf(-s));
        }
    }
    {
        __half* dst = g_Xt + (size_t)b * DD * NN + (size_t)tid * NN + k0;
        #pragma unroll
        for (int w8 = 0; w8 < 4; ++w8) {
            __half2 p[4];
            #pragma unroll
            for (int q = 0; q < 4; ++q)
                p[q] = __floats2half2_rn(sx[w8 * 8 + 2 * q][tid], sx[w8 * 8 + 2 * q + 1][tid]);
            *(uint4*)(dst + w8 * 8) = *(const uint4*)p;
        }
    }
}

// ---------------- K2: fused adjacency-blend + fp16 GEMM + gcn-gate + residual ----------------
// CTA: 64 rows x 256 cols, 256 threads (8 warps, warp tile 32x64), 2 CTAs/SM.
template <int SEL>
__device__ __forceinline__ void adj_mainloop(
    const float* __restrict__ dep32, const float* __restrict__ lat32,
    const __half* __restrict__ Xt, const float* __restrict__ gvec,
    int m0, int tid, float d[2][8][4])
{
    __half* sh = (__half*)smemc;
    const int lane = tid & 31;
    const int warp = tid >> 5;
    const int wm = warp & 1, wn = warp >> 1;
    const int g = lane >> 2, t4 = lane & 3;
    const uint32_t sb = smem_u32(sh);

    int arow = 0, acolq = 0, ai = 0, aj8 = 0;
    float gi = 0.f;
    float gj8[8];
    if (SEL == 0) {
        arow = tid >> 2; acolq = tid & 3;
        gi = gvec[m0 + arow];
    } else {
        ai = tid >> 3; aj8 = (tid & 7) * 8;
        #pragma unroll
        for (int q = 0; q < 8; ++q) gj8[q] = gvec[m0 + aj8 + q];
    }

    float4 dv0, dv1, lv0, lv1;

    auto loadA = [&](int k0) {
        const float* dp;
        const float* lp;
        if (SEL == 0) {
            dp = dep32 + (size_t)(m0 + arow) * NN + k0 + acolq * 8;
            lp = lat32 + (size_t)(m0 + arow) * NN + k0 + acolq * 8;
        } else {
            dp = dep32 + (size_t)(k0 + ai) * NN + m0 + aj8;
            lp = lat32 + (size_t)(k0 + ai) * NN + m0 + aj8;
        }
        dv0 = *(const float4*)dp;  dv1 = *(const float4*)(dp + 4);
        lv0 = *(const float4*)lp;  lv1 = *(const float4*)(lp + 4);
    };
    auto storeA = [&](int stage) {
        __half* As = sh + 2 * B_TILE_H + stage * A_TILE_H;
        float v[8];
        if (SEL == 0) {
            v[0] = fmaf(gi, dv0.x - lv0.x, lv0.x); v[1] = fmaf(gi, dv0.y - lv0.y, lv0.y);
            v[2] = fmaf(gi, dv0.z - lv0.z, lv0.z); v[3] = fmaf(gi, dv0.w - lv0.w, lv0.w);
            v[4] = fmaf(gi, dv1.x - lv1.x, lv1.x); v[5] = fmaf(gi, dv1.y - lv1.y, lv1.y);
            v[6] = fmaf(gi, dv1.z - lv1.z, lv1.z); v[7] = fmaf(gi, dv1.w - lv1.w, lv1.w);
        } else {
            v[0] = fmaf(gj8[0], dv0.x - lv0.x, lv0.x); v[1] = fmaf(gj8[1], dv0.y - lv0.y, lv0.y);
            v[2] = fmaf(gj8[2], dv0.z - lv0.z, lv0.z); v[3] = fmaf(gj8[3], dv0.w - lv0.w, lv0.w);
            v[4] = fmaf(gj8[4], dv1.x - lv1.x, lv1.x); v[5] = fmaf(gj8[5], dv1.y - lv1.y, lv1.y);
            v[6] = fmaf(gj8[6], dv1.z - lv1.z, lv1.z); v[7] = fmaf(gj8[7], dv1.w - lv1.w, lv1.w);
        }
        __half2 h2[4];
        #pragma unroll
        for (int q = 0; q < 4; ++q) h2[q] = __floats2half2_rn(v[2 * q], v[2 * q + 1]);
        uint4 pk = *(const uint4*)h2;
        if (SEL == 0) *(uint4*)(As + arow * ASTR + acolq * 8) = pk;
        else          *(uint4*)(As + ai * MSTR + aj8) = pk;
    };
    auto loadB = [&](int k0, int stage) {
        uint32_t dstb = sb + (uint32_t)(stage * B_TILE_H) * 2;
        #pragma unroll
        for (int u = 0; u < 4; ++u) {
            int e = tid + 256 * u; int row = e >> 2; int colq = e & 3;
            cp16(dstb + (uint32_t)(row * BSTR + colq * 8) * 2,
                 Xt + (size_t)row * NN + k0 + colq * 8);
        }
    };

    loadA(0); loadB(0, 0); CP_COMMIT();
    storeA(0);
    CP_WAIT0(); __syncthreads();

    const int KT = NN / 32;
    for (int kt = 0; kt < KT; ++kt) {
        int cur = kt & 1, nxt = cur ^ 1;
        bool more = (kt + 1) < KT;
        if (more) { loadA((kt + 1) * 32); loadB((kt + 1) * 32, nxt); CP_COMMIT(); }

        const __half* As = sh + 2 * B_TILE_H + cur * A_TILE_H;
        const __half* Bs = sh + cur * B_TILE_H;
        #pragma unroll
        for (int kk = 0; kk < 32; kk += 16) {
            uint32_t a[2][4], bf[8][2];
            #pragma unroll
            for (int fm = 0; fm < 2; ++fm) {
                int m = wm * 32 + fm * 16 + g;
                if (SEL == 0) {
                    a[fm][0] = *(const uint32_t*)(As + m * ASTR + kk + 2 * t4);
                    a[fm][1] = *(const uint32_t*)(As + (m + 8) * ASTR + kk + 2 * t4);
                    a[fm][2] = *(const uint32_t*)(As + m * ASTR + kk + 2 * t4 + 8);
                    a[fm][3] = *(const uint32_t*)(As + (m + 8) * ASTR + kk + 2 * t4 + 8);
                } else {
                    const uint16_t* Au = (const uint16_t*)As;
                    uint32_t k0r = (kk + 2 * t4) * MSTR, k1r = k0r + MSTR;
                    uint32_t k8r = k0r + 8 * MSTR, k9r = k8r + MSTR;
                    a[fm][0] = (uint32_t)Au[k0r + m] | ((uint32_t)Au[k1r + m] << 16);
                    a[fm][1] = (uint32_t)Au[k0r + m + 8] | ((uint32_t)Au[k1r + m + 8] << 16);
                    a[fm][2] = (uint32_t)Au[k8r + m] | ((uint32_t)Au[k9r + m] << 16);
                    a[fm][3] = (uint32_t)Au[k8r + m + 8] | ((uint32_t)Au[k9r + m + 8] << 16);
                }
            }
            #pragma unroll
            for (int fn = 0; fn < 8; ++fn) {
                int n = wn * 64 + fn * 8 + g;
                bf[fn][0] = *(const uint32_t*)(Bs + n * BSTR + kk + 2 * t4);
                bf[fn][1] = *(const uint32_t*)(Bs + n * BSTR + kk + 2 * t4 + 8);
            }
            #pragma unroll
            for (int fm = 0; fm < 2; ++fm)
                #pragma unroll
                for (int fn = 0; fn < 8; ++fn)
                    MMAH(d[fm][fn], a[fm], bf[fn]);
        }
        if (more) { storeA(nxt); CP_WAIT0(); }
        __syncthreads();
    }
}

__global__ void __launch_bounds__(256, 2)
adj_fused_kernel(const float* __restrict__ dep, const float* __restrict__ lat,
                 const float* __restrict__ x_ext, int use_mid,
                 const float* __restrict__ Wgi, const float* __restrict__ bgi,
                 const float* __restrict__ Wgo, const float* __restrict__ bgo) {
    __shared__ float sgate[64];
    const int tid = threadIdx.x;
    const int m0  = blockIdx.x * 64;
    const int b   = blockIdx.y;
    const int sel = blockIdx.z;

    if (tid < 64) sgate[tid] = 0.f;

    const float* dep32 = dep + (size_t)b * NN * NN;
    const float* lat32 = lat + (size_t)b * NN * NN;
    const __half* Xt_b = g_Xt + (size_t)b * DD * NN;
    const float* gvec  = g_gate + b * NN;

    float d[2][8][4] = {};
    if (sel == 0) adj_mainloop<0>(dep32, lat32, Xt_b, gvec, m0, tid, d);
    else          adj_mainloop<1>(dep32, lat32, Xt_b, gvec, m0, tid, d);

    const float* Wg = sel ? Wgo : Wgi;
    const float  bgs = sel ? bgo[0] : bgi[0];
    const float* xres = (use_mid ? g_xmid : x_ext) + (size_t)b * NN * DD;

    const int lane = tid & 31, warp = tid >> 5;
    const int wm = warp & 1, wn = warp >> 1;
    const int g = lane >> 2, c2 = (lane & 3) * 2;

    // ---- gate logit ----
    float p0[2], p1[2];
    #pragma unroll
    for (int fm = 0; fm < 2; ++fm) {
        p0[fm] = 0.f; p1[fm] = 0.f;
        #pragma unroll
        for (int fn = 0; fn < 8; ++fn) {
            int col = wn * 64 + fn * 8 + c2;
            float w0 = Wg[col], w1 = Wg[col + 1];
            p0[fm] += d[fm][fn][0] * w0 + d[fm][fn][1] * w1;
            p1[fm] += d[fm][fn][2] * w0 + d[fm][fn][3] * w1;
        }
    }
    #pragma unroll
    for (int off = 1; off <= 2; off <<= 1) {
        #pragma unroll
        for (int fm = 0; fm < 2; ++fm) {
            p0[fm] += __shfl_xor_sync(0xffffffffu, p0[fm], off);
            p1[fm] += __shfl_xor_sync(0xffffffffu, p1[fm], off);
        }
    }
    if ((lane & 3) == 0) {
        #pragma unroll
        for (int fm = 0; fm < 2; ++fm) {
            atomicAdd(&sgate[wm * 32 + fm * 16 + g],     p0[fm]);
            atomicAdd(&sgate[wm * 32 + fm * 16 + g + 8], p1[fm]);
        }
    }
    __syncthreads();

    // ---- Y = Ax*gate + bg + x -> fp16 ----
    #pragma unroll
    for (int fm = 0; fm < 2; ++fm) {
        int lr = wm * 32 + fm * 16 + g;
        float ga  = 1.f / (1.f + expf(-sgate[lr]));
        float gb2 = 1.f / (1.f + expf(-sgate[lr + 8]));
        size_t grow = (size_t)(b * NN + m0 + lr);
        const float* x0p = xres + (size_t)(m0 + lr) * DD;
        const float* x1p = x0p + 8 * DD;
        __half* yh0 = g_Yh[sel] + grow * DD;
        __half* yh1 = yh0 + 8 * DD;
        #pragma unroll
        for (int fn = 0; fn < 8; ++fn) {
            int col = wn * 64 + fn * 8 + c2;
            float2 xv0 = *(const float2*)(x0p + col);
            float2 xv1 = *(const float2*)(x1p + col);
            __half2 h0 = __floats2half2_rn(d[fm][fn][0] * ga + bgs + xv0.x,
                                           d[fm][fn][1] * ga + bgs + xv0.y);
            __half2 h1 = __floats2half2_rn(d[fm][fn][2] * gb2 + bgs + xv1.x,
                                           d[fm][fn][3] * gb2 + bgs + xv1.y);
            *(__half2*)(yh0 + col) = h0;
            *(__half2*)(yh1 + col) = h1;
        }
    }
}

// ---------------- K3: fc GEMM (fp16, cp.async) + LayerNorm + GELU ----------------
__global__ void __launch_bounds__(512, 1)
fc_ln_kernel(const float* __restrict__ bi, const float* __restrict__ bo,
             const float* __restrict__ gw, const float* __restrict__ bw,
             float* __restrict__ out_ext, int to_mid) {
    __half* sh   = (__half*)smemc;
    float*  hbuf = (float*)smemc;
    const int tid  = threadIdx.x;
    const int lane = tid & 31, warp = tid >> 5;
    const int wm = warp & 1, wq = warp >> 1;
    const int sel = wq >> 2, wn2 = wq & 3;
    const int g = lane >> 2, t4 = lane & 3;
    const int m0 = blockIdx.x * 128;
    const uint32_t sb = smem_u32(sh);

    const __half* base[4] = {
        g_Yh[0] + (size_t)m0 * DD, g_Yh[1] + (size_t)m0 * DD,
        g_W16[0], g_W16[1]
    };

    auto loadStage = [&](int k0, int s) {
        #pragma unroll
        for (int u = 0; u < 4; ++u) {
            int idx = tid + 512 * u;
            int t = idx >> 9, rem = idx & 511;
            int row = rem >> 2, q = rem & 3;
            cp16(sb + (uint32_t)(s * FCS + t * FCT + row * FC_AST + q * 8) * 2,
                 base[t] + (size_t)row * DD + k0 + q * 8);
        }
    };

    float d[4][4][4] = {};

    loadStage(0, 0); CP_COMMIT();
    CP_WAIT0(); __syncthreads();

    const int KT = DD / 32;
    for (int kt = 0; kt < KT; ++kt) {
        int cur = kt & 1, nxt = cur ^ 1;
        bool more = (kt + 1) < KT;
        if (more) { loadStage((kt + 1) * 32, nxt); CP_COMMIT(); }

        const __half* Bw = sh + cur * FCS + (2 + sel) * FCT;
        const __half* As = sh + cur * FCS + sel * FCT;
        #pragma unroll
        for (int kk = 0; kk < 32; kk += 16) {
            uint32_t bf[4][2];
            #pragma unroll
            for (int fn = 0; fn < 4; ++fn) {
                int n = wn2 * 32 + fn * 8 + g;
                bf[fn][0] = *(const uint32_t*)(Bw + n * FC_AST + kk + 2 * t4);
                bf[fn][1] = *(const uint32_t*)(Bw + n * FC_AST + kk + 2 * t4 + 8);
            }
            uint32_t a[4][4];
            #pragma unroll
            for (int fm = 0; fm < 4; ++fm) {
                int m = wm * 64 + fm * 16 + g;
                a[fm][0] = *(const uint32_t*)(As + m * FC_AST + kk + 2 * t4);
                a[fm][1] = *(const uint32_t*)(As + (m + 8) * FC_AST + kk + 2 * t4);
                a[fm][2] = *(const uint32_t*)(As + m * FC_AST + kk + 2 * t4 + 8);
                a[fm][3] = *(const uint32_t*)(As + (m + 8) * FC_AST + kk + 2 * t4 + 8);
            }
            #pragma unroll
            for (int fm = 0; fm < 4; ++fm)
                #pragma unroll
                for (int fn = 0; fn < 4; ++fn)
                    MMAH(d[fm][fn], a[fm], bf[fn]);
        }
        if (more) CP_WAIT0();
        __syncthreads();
    }

    // ---- write h into smem hbuf (stride 260) ----
    const float* bias = sel ? bo : bi;
    const int c2 = t4 * 2;
    #pragma unroll
    for (int fm = 0; fm < 4; ++fm) {
        int lr = wm * 64 + fm * 16 + g;
        #pragma unroll
        for (int fn = 0; fn < 4; ++fn) {
            int cl = wn2 * 32 + fn * 8 + c2;
            int colg = sel * 128 + cl;
            float b0 = 2.f * bias[cl], b1 = 2.f * bias[cl + 1];
            hbuf[lr * 260 + colg]           = d[fm][fn][0] + b0;
            hbuf[lr * 260 + colg + 1]       = d[fm][fn][1] + b1;
            hbuf[(lr + 8) * 260 + colg]     = d[fm][fn][2] + b0;
            hbuf[(lr + 8) * 260 + colg + 1] = d[fm][fn][3] + b1;
        }
    }
    __syncthreads();

    // ---- LayerNorm(256) + exact GELU, 4 threads per row ----
    {
        int row = tid >> 2, p = tid & 3;
        float s = 0.f, s2 = 0.f;
        #pragma unroll
        for (int j = 0; j < 16; ++j) {
            float4 v = *(const float4*)(hbuf + row * 260 + p * 4 + 16 * j);
            s += v.x + v.y + v.z + v.w;
            s2 += v.x * v.x + v.y * v.y + v.z * v.z + v.w * v.w;
        }
        #pragma unroll
        for (int off = 1; off <= 2; off <<= 1) {
            s  += __shfl_xor_sync(0xffffffffu, s,  off);
            s2 += __shfl_xor_sync(0xffffffffu, s2, off);
        }
        float mu  = s * (1.f / DD);
        float var = s2 * (1.f / DD) - mu * mu;
        float rr  = rsqrtf(var + 1e-5f);
        float* outp = (to_mid ? g_xmid : out_ext) + (size_t)(m0 + row) * DD;
        #pragma unroll
        for (int j = 0; j < 16; ++j) {
            int col = p * 4 + 16 * j;
            float4 v = *(const float4*)(hbuf + row * 260 + col);
            float4 o;
            float hn;
            hn = (v.x - mu) * rr * gw[col]     + bw[col];
            o.x = 0.5f * hn * (1.f + erff(hn * 0.70710678118654752f));
            hn = (v.y - mu) * rr * gw[col + 1] + bw[col + 1];
            o.y = 0.5f * hn * (1.f + erff(hn * 0.70710678118654752f));
            hn = (v.z - mu) * rr * gw[col + 2] + bw[col + 2];
            o.z = 0.5f * hn * (1.f + erff(hn * 0.70710678118654752f));
            hn = (v.w - mu) * rr * gw[col + 3] + bw[col + 3];
            o.w = 0.5f * hn * (1.f + erff(hn * 0.70710678118654752f));
            *(float4*)(outp + col) = o;
        }
    }
}

// ---------------- host launcher ----------------
extern "C" void kernel_launch(void* const* d_in, const int* in_sizes, int n_in,
                              void* d_out, int out_size) {
    (void)in_sizes; (void)n_in; (void)out_size;
    const float* x0  = (const float*)d_in[0];
    const float* lat = (const float*)d_in[1];
    const float* dep = (const float*)d_in[2];
    const float* rg  = (const float*)d_in[3];
    const float* Wgi = (const float*)d_in[4];
    const float* bgi = (const float*)d_in[5];
    const float* Wgo = (const float*)d_in[6];
    const float* bgo = (const float*)d_in[7];
    const float* Wi  = (const float*)d_in[8];
    const float* bi  = (const float*)d_in[9];
    const float* Wo  = (const float*)d_in[10];
    const float* bo  = (const float*)d_in[11];
    const float* lng = (const float*)d_in[12];
    const float* lnb = (const float*)d_in[13];
    float* out = (float*)d_out;

    cudaFuncSetAttribute(adj_fused_kernel, cudaFuncAttributeMaxDynamicSharedMemorySize, ADJ_SMEM);
    cudaFuncSetAttribute(fc_ln_kernel,     cudaFuncAttributeMaxDynamicSharedMemorySize, FC_SMEM);

    for (int l = 0; l < LL; l++) {
        int use_mid = (l != 0);
        int to_mid  = (l != LL - 1);

        dim3 gP(NN / 32, Bq);
        prep_kernel<<<gP, 256>>>(x0, use_mid, rg + l * DD);

        w16_kernel<<<HH * DD / (256 * 4), 256>>>(Wi + (size_t)l * HH * DD,
                                                 Wo + (size_t)l * HH * DD);

        dim3 gM(NN / 64, Bq, 2);
        adj_fused_kernel<<<gM, 256, ADJ_SMEM>>>(dep, lat, x0, use_mid,
                                                Wgi + l * DD, bgi + l,
                                                Wgo + l * DD, bgo + l);

        fc_ln_kernel<<<(Bq * NN) / 128, 512, FC_SMEM>>>(
            bi + l * HH, bo + l * HH,
            lng + l * 2 * HH, lnb + l * 2 * HH,
            out, to_mid);
    }
}